// round 1
// baseline (speedup 1.0000x reference)
#include <cuda_runtime.h>
#include <math.h>

#define BATCH 1024
#define INPUT_SIZE 512
#define HIDDEN 1024
#define N_QP 64
#define M_QP 128
#define QP_ITER 50
#define N_P 2080          // 64*65/2
#define N_HMAT 8192       // 128*64
#define N_OUT 10464       // 2080 + 64 + 8192 + 128

// Intermediate buffers (no allocations allowed)
__device__ float g_h1[BATCH * HIDDEN];
__device__ float g_h2[BATCH * HIDDEN];
__device__ float g_out3[BATCH * N_OUT];

// ---------------------------------------------------------------------------
// Tiled fp32 SGEMM with fused bias (+ optional ReLU).
// C[M,N] = A[M,K] @ B[K,N] + bias[N]
// Block: 64x64 tile, BK=16, 256 threads, 4x4 per-thread micro-tile.
// M must be a multiple of 64, K a multiple of 16, N a multiple of 4 (guarded).
// ---------------------------------------------------------------------------
template <bool RELU>
__global__ __launch_bounds__(256)
void sgemm_bias(const float* __restrict__ A, const float* __restrict__ B,
                const float* __restrict__ bias, float* __restrict__ C,
                int M, int N, int K)
{
    __shared__ float As[16 * 65];   // transposed: As[k][m], pad 65
    __shared__ float Bs[16 * 64];   // Bs[k][n]

    const int tid = threadIdx.x;
    const int tx = tid & 15;        // n group
    const int ty = tid >> 4;        // m group
    const int m0 = blockIdx.y * 64;
    const int n0 = blockIdx.x * 64;

    const int aRow = tid >> 2;      // 0..63
    const int aC4  = tid & 3;       // 0..3 (float4 column group)
    const int bRow = tid >> 4;      // 0..15
    const int bC4  = tid & 15;      // 0..15 (float4 column group)

    float acc[4][4] = {};

    for (int k0 = 0; k0 < K; k0 += 16) {
        // Load A tile (64 x 16) as float4 per thread
        float4 av = *(const float4*)&A[(size_t)(m0 + aRow) * K + k0 + aC4 * 4];
        // Load B tile (16 x 64) as float4 per thread (guard N boundary)
        int bn = n0 + bC4 * 4;
        float4 bv = make_float4(0.f, 0.f, 0.f, 0.f);
        if (bn < N) bv = *(const float4*)&B[(size_t)(k0 + bRow) * N + bn];

        __syncthreads();   // protect previous tile's compute
        As[(aC4 * 4 + 0) * 65 + aRow] = av.x;
        As[(aC4 * 4 + 1) * 65 + aRow] = av.y;
        As[(aC4 * 4 + 2) * 65 + aRow] = av.z;
        As[(aC4 * 4 + 3) * 65 + aRow] = av.w;
        *(float4*)&Bs[bRow * 64 + bC4 * 4] = bv;
        __syncthreads();

        #pragma unroll
        for (int k = 0; k < 16; ++k) {
            float4 bb = *(const float4*)&Bs[k * 64 + tx * 4];
            float a0 = As[k * 65 + ty * 4 + 0];
            float a1 = As[k * 65 + ty * 4 + 1];
            float a2 = As[k * 65 + ty * 4 + 2];
            float a3 = As[k * 65 + ty * 4 + 3];
            acc[0][0] = fmaf(a0, bb.x, acc[0][0]);
            acc[0][1] = fmaf(a0, bb.y, acc[0][1]);
            acc[0][2] = fmaf(a0, bb.z, acc[0][2]);
            acc[0][3] = fmaf(a0, bb.w, acc[0][3]);
            acc[1][0] = fmaf(a1, bb.x, acc[1][0]);
            acc[1][1] = fmaf(a1, bb.y, acc[1][1]);
            acc[1][2] = fmaf(a1, bb.z, acc[1][2]);
            acc[1][3] = fmaf(a1, bb.w, acc[1][3]);
            acc[2][0] = fmaf(a2, bb.x, acc[2][0]);
            acc[2][1] = fmaf(a2, bb.y, acc[2][1]);
            acc[2][2] = fmaf(a2, bb.z, acc[2][2]);
            acc[2][3] = fmaf(a2, bb.w, acc[2][3]);
            acc[3][0] = fmaf(a3, bb.x, acc[3][0]);
            acc[3][1] = fmaf(a3, bb.y, acc[3][1]);
            acc[3][2] = fmaf(a3, bb.z, acc[3][2]);
            acc[3][3] = fmaf(a3, bb.w, acc[3][3]);
        }
    }

    #pragma unroll
    for (int ii = 0; ii < 4; ++ii) {
        int m = m0 + ty * 4 + ii;
        #pragma unroll
        for (int jj = 0; jj < 4; ++jj) {
            int n = n0 + tx * 4 + jj;
            if (n < N) {
                float v = acc[ii][jj] + bias[n];
                if (RELU) v = fmaxf(v, 0.f);
                C[(size_t)m * N + n] = v;
            }
        }
    }
}

// ---------------------------------------------------------------------------
// Per-batch QP solver. One CTA (256 threads) per batch item.
// Layout of out3 row: [P_params(2080) | q(64) | H(128x64) | b(128)]
// ---------------------------------------------------------------------------
__global__ __launch_bounds__(256)
void solver_kernel(const float* __restrict__ out3, float* __restrict__ xs)
{
    extern __shared__ float smdyn[];
    float* sH    = smdyn;              // 128*65
    float* sL    = sH   + 128 * 65;    // 64*65
    float* sM    = sL   + 64 * 65;     // 64*65 (P, then M, then Minv in place)
    float* sv    = sM   + 64 * 65;     // 64
    float* sw    = sv   + 64;          // 128
    float* sq    = sw   + 128;         // 64
    float* sb    = sq   + 64;          // 128
    float* slam  = sb   + 128;         // 128
    float* sxp   = slam + 128;         // 64
    float* sxbar = sxp  + 64;          // 64
    float* st    = sxbar+ 64;          // 64
    float* sred  = st   + 64;          // 128

    __shared__ float s_scal;
    __shared__ float s_tau;

    const int tid = threadIdx.x;
    const int bidx = blockIdx.x;
    const float* row = out3 + (size_t)bidx * N_OUT;

    // ---- Load H (stride-65 padded), q, b; zero L ----
    for (int idx = tid; idx < N_HMAT; idx += 256) {
        sH[(idx >> 6) * 65 + (idx & 63)] = row[N_P + N_QP + idx];
    }
    if (tid < 64)  sq[tid] = row[N_P + tid];
    if (tid < 128) sb[tid] = row[N_P + N_QP + N_HMAT + tid];
    for (int idx = tid; idx < 64 * 65; idx += 256) sL[idx] = 0.f;
    __syncthreads();

    // ---- Scatter Cholesky params into L (softplus on diagonal) ----
    for (int idx = tid; idx < N_P; idx += 256) {
        float p = row[idx];
        int r = (int)((sqrtf(8.f * (float)idx + 1.f) - 1.f) * 0.5f);
        while ((r * (r + 1)) / 2 > idx) --r;
        while (((r + 1) * (r + 2)) / 2 <= idx) ++r;
        int c = idx - (r * (r + 1)) / 2;
        float val;
        if (c == r) {
            float sp = fmaxf(p, 0.f) + log1pf(expf(-fabsf(p)));  // softplus
            val = 0.1f + sp;                                      // sqrt(0.01)=0.1
        } else {
            val = p;
        }
        sL[r * 65 + c] = val;
    }
    __syncthreads();

    // ---- P = L L^T  into sM ----
    for (int e = tid; e < 4096; e += 256) {
        int i = e >> 6, j = e & 63;
        float a0 = 0.f, a1 = 0.f, a2 = 0.f, a3 = 0.f;
        const float* li = &sL[i * 65];
        const float* lj = &sL[j * 65];
        #pragma unroll 8
        for (int k = 0; k < 64; k += 4) {
            a0 = fmaf(li[k + 0], lj[k + 0], a0);
            a1 = fmaf(li[k + 1], lj[k + 1], a1);
            a2 = fmaf(li[k + 2], lj[k + 2], a2);
            a3 = fmaf(li[k + 3], lj[k + 3], a3);
        }
        sM[i * 65 + j] = (a0 + a1) + (a2 + a3);
    }

    // ---- Power iteration on H^T H ----
    if (tid < 64) sv[tid] = 0.125f;   // 1/sqrt(64)
    __syncthreads();

    for (int pit = 0; pit < 10; ++pit) {
        if (tid < 128) {  // w = H v
            const float* hr = &sH[tid * 65];
            float a0 = 0.f, a1 = 0.f, a2 = 0.f, a3 = 0.f;
            #pragma unroll 8
            for (int n = 0; n < 64; n += 4) {
                a0 = fmaf(hr[n + 0], sv[n + 0], a0);
                a1 = fmaf(hr[n + 1], sv[n + 1], a1);
                a2 = fmaf(hr[n + 2], sv[n + 2], a2);
                a3 = fmaf(hr[n + 3], sv[n + 3], a3);
            }
            sw[tid] = (a0 + a1) + (a2 + a3);
        }
        __syncthreads();
        if (tid < 64) {   // t = H^T w
            float a0 = 0.f, a1 = 0.f, a2 = 0.f, a3 = 0.f;
            #pragma unroll 8
            for (int m = 0; m < 128; m += 4) {
                a0 = fmaf(sH[(m + 0) * 65 + tid], sw[m + 0], a0);
                a1 = fmaf(sH[(m + 1) * 65 + tid], sw[m + 1], a1);
                a2 = fmaf(sH[(m + 2) * 65 + tid], sw[m + 2], a2);
                a3 = fmaf(sH[(m + 3) * 65 + tid], sw[m + 3], a3);
            }
            float acc = (a0 + a1) + (a2 + a3);
            st[tid] = acc;
            sred[tid] = acc * acc;
        }
        __syncthreads();
        if (tid == 0) {
            float s = 0.f;
            for (int i = 0; i < 64; ++i) s += sred[i];
            s_scal = sqrtf(s) + 1e-12f;
        }
        __syncthreads();
        if (tid < 64) sv[tid] = st[tid] / s_scal;
        __syncthreads();
    }

    // ---- sn = ||H v|| + 1e-6 ; tau = 0.9 / sn ----
    if (tid < 128) {
        const float* hr = &sH[tid * 65];
        float a0 = 0.f, a1 = 0.f, a2 = 0.f, a3 = 0.f;
        #pragma unroll 8
        for (int n = 0; n < 64; n += 4) {
            a0 = fmaf(hr[n + 0], sv[n + 0], a0);
            a1 = fmaf(hr[n + 1], sv[n + 1], a1);
            a2 = fmaf(hr[n + 2], sv[n + 2], a2);
            a3 = fmaf(hr[n + 3], sv[n + 3], a3);
        }
        float acc = (a0 + a1) + (a2 + a3);
        sred[tid] = acc * acc;
    }
    __syncthreads();
    if (tid == 0) {
        float s = 0.f;
        for (int i = 0; i < 128; ++i) s += sred[i];
        s_tau = 0.9f / (sqrtf(s) + 1e-6f);
    }
    __syncthreads();
    const float tau = s_tau;
    const float sig = tau;

    // ---- M = I + tau * P (in place over P) ----
    for (int e = tid; e < 4096; e += 256) {
        int i = e >> 6, j = e & 63;
        float m = tau * sM[i * 65 + j];
        if (i == j) m += 1.f;
        sM[i * 65 + j] = m;
    }
    __syncthreads();

    // ---- In-place Gauss-Jordan inverse (SPD, no pivoting needed) ----
    {
        const int i  = tid & 63;
        const int jb = (tid >> 6) << 4;   // 0,16,32,48
        for (int k = 0; k < 64; ++k) {
            if (tid == 0) s_scal = 1.f / sM[k * 65 + k];
            __syncthreads();
            const float piv = s_scal;
            // read elimination factor (column k untouched by normalization)
            float f = (i != k) ? sM[i * 65 + k] : 0.f;
            // normalize row k
            if (tid < 64) {
                sM[k * 65 + tid] = (tid == k) ? piv : sM[k * 65 + tid] * piv;
            }
            __syncthreads();
            if (i != k) {
                #pragma unroll
                for (int jj = 0; jj < 16; ++jj) {
                    int j = jb + jj;
                    if (j != k) {
                        sM[i * 65 + j] = fmaf(-f, sM[k * 65 + j], sM[i * 65 + j]);
                    }
                }
                if (k >= jb && k < jb + 16) sM[i * 65 + k] = -f * piv;
            }
            __syncthreads();
        }
    }

    // ---- QP iterations ----
    if (tid < 64) { sxp[tid] = 0.f; sxbar[tid] = 0.f; }
    if (tid < 128) slam[tid] = 0.f;
    __syncthreads();

    for (int it = 0; it < QP_ITER; ++it) {
        // lam = relu(lam - sig*(H xbar + b))
        if (tid < 128) {
            const float* hr = &sH[tid * 65];
            float a0 = 0.f, a1 = 0.f, a2 = 0.f, a3 = 0.f;
            #pragma unroll 8
            for (int n = 0; n < 64; n += 4) {
                a0 = fmaf(hr[n + 0], sxbar[n + 0], a0);
                a1 = fmaf(hr[n + 1], sxbar[n + 1], a1);
                a2 = fmaf(hr[n + 2], sxbar[n + 2], a2);
                a3 = fmaf(hr[n + 3], sxbar[n + 3], a3);
            }
            float acc = (a0 + a1) + (a2 + a3) + sb[tid];
            slam[tid] = fmaxf(0.f, slam[tid] - sig * acc);
        }
        __syncthreads();
        // t = xp + tau*(H^T lam - q)
        if (tid < 64) {
            float a0 = 0.f, a1 = 0.f, a2 = 0.f, a3 = 0.f;
            #pragma unroll 8
            for (int m = 0; m < 128; m += 4) {
                a0 = fmaf(sH[(m + 0) * 65 + tid], slam[m + 0], a0);
                a1 = fmaf(sH[(m + 1) * 65 + tid], slam[m + 1], a1);
                a2 = fmaf(sH[(m + 2) * 65 + tid], slam[m + 2], a2);
                a3 = fmaf(sH[(m + 3) * 65 + tid], slam[m + 3], a3);
            }
            float acc = (a0 + a1) + (a2 + a3);
            st[tid] = sxp[tid] + tau * (acc - sq[tid]);
        }
        __syncthreads();
        // xn = Minv t ; xbar = 2 xn - xp ; xp = xn
        if (tid < 64) {
            const float* mr = &sM[tid * 65];
            float a0 = 0.f, a1 = 0.f, a2 = 0.f, a3 = 0.f;
            #pragma unroll 8
            for (int j = 0; j < 64; j += 4) {
                a0 = fmaf(mr[j + 0], st[j + 0], a0);
                a1 = fmaf(mr[j + 1], st[j + 1], a1);
                a2 = fmaf(mr[j + 2], st[j + 2], a2);
                a3 = fmaf(mr[j + 3], st[j + 3], a3);
            }
            float xn = (a0 + a1) + (a2 + a3);
            float xpold = sxp[tid];
            sxp[tid] = xn;
            sxbar[tid] = 2.f * xn - xpold;
        }
        __syncthreads();
    }

    if (tid < 64) xs[(size_t)bidx * N_QP + tid] = sxp[tid];
}

// ---------------------------------------------------------------------------
// Launch
// ---------------------------------------------------------------------------
extern "C" void kernel_launch(void* const* d_in, const int* in_sizes, int n_in,
                              void* d_out, int out_size)
{
    const float* x  = (const float*)d_in[0];
    const float* W1 = (const float*)d_in[1];
    const float* b1 = (const float*)d_in[2];
    const float* W2 = (const float*)d_in[3];
    const float* b2 = (const float*)d_in[4];
    const float* W3 = (const float*)d_in[5];
    const float* b3 = (const float*)d_in[6];
    float* out = (float*)d_out;

    float *p_h1, *p_h2, *p_out3;
    cudaGetSymbolAddress((void**)&p_h1, g_h1);
    cudaGetSymbolAddress((void**)&p_h2, g_h2);
    cudaGetSymbolAddress((void**)&p_out3, g_out3);

    // GEMM1: h1 = relu(x @ W1 + b1)   [1024,512] x [512,1024]
    {
        dim3 grid(HIDDEN / 64, BATCH / 64);
        sgemm_bias<true><<<grid, 256>>>(x, W1, b1, p_h1, BATCH, HIDDEN, INPUT_SIZE);
    }
    // GEMM2: h2 = relu(h1 @ W2 + b2)  [1024,1024] x [1024,1024]
    {
        dim3 grid(HIDDEN / 64, BATCH / 64);
        sgemm_bias<true><<<grid, 256>>>(p_h1, W2, b2, p_h2, BATCH, HIDDEN, HIDDEN);
    }
    // GEMM3: out3 = h2 @ W3 + b3      [1024,1024] x [1024,10464]
    {
        dim3 grid((N_OUT + 63) / 64, BATCH / 64);
        sgemm_bias<false><<<grid, 256>>>(p_h2, W3, b3, p_out3, BATCH, N_OUT, HIDDEN);
    }
    // Solver: one CTA per batch item
    {
        const int smem_floats = 128 * 65 + 64 * 65 + 64 * 65
                              + 64 + 128 + 64 + 128 + 128 + 64 + 64 + 64 + 128;
        const size_t smem_bytes = (size_t)smem_floats * sizeof(float);
        cudaFuncSetAttribute(solver_kernel,
                             cudaFuncAttributeMaxDynamicSharedMemorySize,
                             (int)smem_bytes);
        solver_kernel<<<BATCH, 256, smem_bytes>>>(p_out3, out);
    }
}